// round 1
// baseline (speedup 1.0000x reference)
#include <cuda_runtime.h>
#include <cuda_bf16.h>
#include <math.h>

// Problem constants
#define BB 2
#define TT 2048
#define DD 2048
#define HH 16
#define KD 128
#define VD 128
#define BT (BB*TT)          // 4096
#define HK (HH*KD)          // 2048
#define HV (HH*VD)          // 2048

// ---------------- scratch (device globals; no allocation allowed) ----------------
__device__ float g_Q[BT*HK];
__device__ float g_K[BT*HK];
__device__ float g_V[BT*HV];
__device__ float g_Qc[BT*HK];
__device__ float g_Kc[BT*HK];
__device__ float g_Vc[BT*HV];
__device__ float g_EG[BT*HK];     // g_raw, then overwritten in-place with exp(g)
__device__ float g_F1[BT*VD];
__device__ float g_G1[BT*VD];
__device__ float g_Gate[BT*HV];
__device__ float g_Beta[BT*HH];
__device__ float g_Y[BT*HV];

// ---------------- fp32 tiled GEMM: C[M,N] = A[M,Kd] * B[N,Kd]^T ----------------
// Assumes M%128==0, N%128==0, Kd%16==0 (true for every call here).
#define GBM 128
#define GBN 128
#define GBK 16
#define GPAD 132

__global__ __launch_bounds__(256) void sgemm_nt(const float* __restrict__ A,
                                                const float* __restrict__ B,
                                                float* __restrict__ C,
                                                int M, int N, int Kd)
{
    __shared__ float As[GBK][GPAD];
    __shared__ float Bs[GBK][GPAD];
    const int tid = threadIdx.x;
    const int m0 = blockIdx.y * GBM;
    const int n0 = blockIdx.x * GBN;
    const int tr = (tid >> 4) << 3;   // 0..120 step 8
    const int tc = (tid & 15) << 3;   // 0..120 step 8

    float acc[8][8];
#pragma unroll
    for (int i = 0; i < 8; i++)
#pragma unroll
        for (int j = 0; j < 8; j++) acc[i][j] = 0.f;

    for (int k0 = 0; k0 < Kd; k0 += GBK) {
#pragma unroll
        for (int l = 0; l < 2; l++) {
            int lin = tid + l * 256;
            int row = lin >> 2;       // 0..127
            int c4  = lin & 3;        // float4 column
            float4 a = *(const float4*)&A[(size_t)(m0 + row) * Kd + k0 + c4 * 4];
            As[c4*4+0][row] = a.x; As[c4*4+1][row] = a.y;
            As[c4*4+2][row] = a.z; As[c4*4+3][row] = a.w;
            float4 b = *(const float4*)&B[(size_t)(n0 + row) * Kd + k0 + c4 * 4];
            Bs[c4*4+0][row] = b.x; Bs[c4*4+1][row] = b.y;
            Bs[c4*4+2][row] = b.z; Bs[c4*4+3][row] = b.w;
        }
        __syncthreads();
#pragma unroll
        for (int kk = 0; kk < GBK; kk++) {
            float ra[8], rb[8];
            *(float4*)&ra[0] = *(const float4*)&As[kk][tr];
            *(float4*)&ra[4] = *(const float4*)&As[kk][tr + 4];
            *(float4*)&rb[0] = *(const float4*)&Bs[kk][tc];
            *(float4*)&rb[4] = *(const float4*)&Bs[kk][tc + 4];
#pragma unroll
            for (int i = 0; i < 8; i++)
#pragma unroll
                for (int j = 0; j < 8; j++)
                    acc[i][j] = fmaf(ra[i], rb[j], acc[i][j]);
        }
        __syncthreads();
    }
#pragma unroll
    for (int i = 0; i < 8; i++) {
        float4 v0 = make_float4(acc[i][0], acc[i][1], acc[i][2], acc[i][3]);
        float4 v1 = make_float4(acc[i][4], acc[i][5], acc[i][6], acc[i][7]);
        size_t base = (size_t)(m0 + tr + i) * N + n0 + tc;
        *(float4*)&C[base]     = v0;
        *(float4*)&C[base + 4] = v1;
    }
}

// ---------------- beta = sigmoid(x @ Wb^T), Wb: [H, D] ----------------
__global__ __launch_bounds__(256) void beta_kernel(const float* __restrict__ x,
                                                   const float* __restrict__ Wb,
                                                   float* __restrict__ Beta)
{
    const int m = blockIdx.x;
    const int tid = threadIdx.x;
    float acc[HH];
#pragma unroll
    for (int h = 0; h < HH; h++) acc[h] = 0.f;
    for (int d = tid; d < DD; d += 256) {
        float xv = x[(size_t)m * DD + d];
#pragma unroll
        for (int h = 0; h < HH; h++)
            acc[h] = fmaf(xv, Wb[(size_t)h * DD + d], acc[h]);
    }
    __shared__ float red[HH][9];
    const int warp = tid >> 5, lane = tid & 31;
#pragma unroll
    for (int h = 0; h < HH; h++) {
        float v = acc[h];
#pragma unroll
        for (int mask = 16; mask > 0; mask >>= 1)
            v += __shfl_xor_sync(0xffffffffu, v, mask);
        if (lane == 0) red[h][warp] = v;
    }
    __syncthreads();
    if (tid < HH) {
        float s = 0.f;
#pragma unroll
        for (int w = 0; w < 8; w++) s += red[tid][w];
        Beta[(size_t)m * HH + tid] = 1.f / (1.f + expf(-s));
    }
}

// ---------------- causal depthwise conv (k=4) + silu (+ optional l2norm) ----------------
// in/out: [BT, H*C] with C=128; w: [H, C, 4]
__global__ __launch_bounds__(128) void convnorm_kernel(const float* __restrict__ in,
                                                       const float* __restrict__ w,
                                                       float* __restrict__ out,
                                                       int doNorm)
{
    const int m = blockIdx.x >> 4;
    const int h = blockIdx.x & 15;
    const int t = m & (TT - 1);
    const int c = threadIdx.x;
    const int col = h * 128 + c;
    const float* wp = &w[(size_t)(h * 128 + c) * 4];
    float acc = 0.f;
#pragma unroll
    for (int i = 0; i < 4; i++) {
        int tt = t - 3 + i;
        if (tt >= 0)
            acc = fmaf(in[(size_t)(m - 3 + i) * 2048 + col], wp[i], acc);
    }
    acc = acc / (1.f + expf(-acc));   // silu
    if (doNorm) {
        float ss = acc * acc;
#pragma unroll
        for (int mask = 16; mask > 0; mask >>= 1)
            ss += __shfl_xor_sync(0xffffffffu, ss, mask);
        __shared__ float sred[4];
        if ((threadIdx.x & 31) == 0) sred[threadIdx.x >> 5] = ss;
        __syncthreads();
        float tot = sred[0] + sred[1] + sred[2] + sred[3];
        float nrm = sqrtf(tot);
        acc = acc / fmaxf(nrm, 1e-12f);
    }
    out[(size_t)m * 2048 + col] = acc;
}

// ---------------- decay: EG = exp(-exp(A_log[h]) * softplus(g_raw + dt_bias)) (in-place) ----------------
__global__ void decay_kernel(const float* __restrict__ A_log,
                             const float* __restrict__ dt_bias,
                             float* __restrict__ G)
{
    int idx = blockIdx.x * blockDim.x + threadIdx.x;
    if (idx >= BT * HK) return;
    int col = idx & (HK - 1);
    int h = col >> 7;
    float xv = G[idx] + dt_bias[col];
    float sp = (xv > 20.f) ? xv : log1pf(expf(xv));
    G[idx] = expf(-expf(A_log[h]) * sp);
}

// ---------------- KDA delta-rule scan ----------------
// grid = B*H*4 (V split in 4 chunks of 32 cols), 128 threads.
// thread: col j = chunk*32 + (tid>>2), row-group p = tid&3 owns rows p*32..p*32+31 of S.
#define SCH 16
__global__ __launch_bounds__(128) void scan_kernel(const float* __restrict__ Qc,
                                                   const float* __restrict__ Kc,
                                                   const float* __restrict__ Vc,
                                                   const float* __restrict__ EG,
                                                   const float* __restrict__ Beta,
                                                   float* __restrict__ Y)
{
    const int chunkV = blockIdx.x & 3;
    const int bh = blockIdx.x >> 2;
    const int b = bh >> 4, h = bh & 15;
    const int tid = threadIdx.x;
    const int p = tid & 3;
    const int jj = tid >> 2;                    // 0..31
    const int col = h * 128 + chunkV * 32 + jj;

    __shared__ float sk[SCH][144];
    __shared__ float sq[SCH][144];
    __shared__ float se[SCH][144];
    __shared__ float sv[SCH][32];
    __shared__ float sb[SCH];

    float S[32];
#pragma unroll
    for (int r = 0; r < 32; r++) S[r] = 0.f;

    const int pos = tid + ((tid >> 5) << 2);    // skewed layout (+4 floats per 32)
    const int pbase = p * 36;

    for (int t0 = 0; t0 < TT; t0 += SCH) {
        __syncthreads();
#pragma unroll 4
        for (int s = 0; s < SCH; s++) {
            size_t off = (size_t)(b * TT + t0 + s) * 2048 + h * 128 + tid;
            sk[s][pos] = Kc[off];
            sq[s][pos] = Qc[off];
            se[s][pos] = EG[off];
        }
        if (tid < 32) {
#pragma unroll 4
            for (int s = 0; s < SCH; s++)
                sv[s][tid] = Vc[(size_t)(b * TT + t0 + s) * 2048 + h * 128 + chunkV * 32 + tid];
        }
        if (tid < SCH)
            sb[tid] = Beta[(size_t)(b * TT + t0 + tid) * HH + h];
        __syncthreads();

        for (int s = 0; s < SCH; s++) {
            const float* kp = &sk[s][pbase];
            const float* ep = &se[s][pbase];
            const float* qp = &sq[s][pbase];
            float d0 = 0.f, d1 = 0.f, d2 = 0.f, d3 = 0.f;
#pragma unroll
            for (int r = 0; r < 32; r += 4) {
                float s0 = S[r + 0] * ep[r + 0];
                float s1 = S[r + 1] * ep[r + 1];
                float s2 = S[r + 2] * ep[r + 2];
                float s3 = S[r + 3] * ep[r + 3];
                S[r + 0] = s0; S[r + 1] = s1; S[r + 2] = s2; S[r + 3] = s3;
                d0 = fmaf(kp[r + 0], s0, d0);
                d1 = fmaf(kp[r + 1], s1, d1);
                d2 = fmaf(kp[r + 2], s2, d2);
                d3 = fmaf(kp[r + 3], s3, d3);
            }
            float dot = (d0 + d1) + (d2 + d3);
            dot += __shfl_xor_sync(0xffffffffu, dot, 1);
            dot += __shfl_xor_sync(0xffffffffu, dot, 2);
            float u = sb[s] * (sv[s][jj] - dot);
            float o0 = 0.f, o1 = 0.f, o2 = 0.f, o3 = 0.f;
#pragma unroll
            for (int r = 0; r < 32; r += 4) {
                S[r + 0] = fmaf(kp[r + 0], u, S[r + 0]);
                S[r + 1] = fmaf(kp[r + 1], u, S[r + 1]);
                S[r + 2] = fmaf(kp[r + 2], u, S[r + 2]);
                S[r + 3] = fmaf(kp[r + 3], u, S[r + 3]);
                o0 = fmaf(qp[r + 0], S[r + 0], o0);
                o1 = fmaf(qp[r + 1], S[r + 1], o1);
                o2 = fmaf(qp[r + 2], S[r + 2], o2);
                o3 = fmaf(qp[r + 3], S[r + 3], o3);
            }
            float od = (o0 + o1) + (o2 + o3);
            od += __shfl_xor_sync(0xffffffffu, od, 1);
            od += __shfl_xor_sync(0xffffffffu, od, 2);
            if (p == 0)
                Y[(size_t)(b * TT + t0 + s) * 2048 + col] = od;
        }
    }
}

// ---------------- RMS norm over V, * o_norm_w, * sigmoid(gate + bg) (in-place on Y) ----------------
__global__ __launch_bounds__(128) void rmsgate_kernel(float* __restrict__ Y,
                                                      const float* __restrict__ Gate,
                                                      const float* __restrict__ bg,
                                                      const float* __restrict__ onw)
{
    const int m = blockIdx.x >> 4;
    const int h = blockIdx.x & 15;
    const int c = threadIdx.x;
    const int col = h * 128 + c;
    float y = Y[(size_t)m * 2048 + col];
    float ss = y * y;
#pragma unroll
    for (int mask = 16; mask > 0; mask >>= 1)
        ss += __shfl_xor_sync(0xffffffffu, ss, mask);
    __shared__ float sred[4];
    if ((threadIdx.x & 31) == 0) sred[threadIdx.x >> 5] = ss;
    __syncthreads();
    float tot = sred[0] + sred[1] + sred[2] + sred[3];
    float r = rsqrtf(tot * (1.f / 128.f) + 1.1920929e-07f);
    float g = Gate[(size_t)m * 2048 + col] + bg[col];
    Y[(size_t)m * 2048 + col] = y * r * onw[c] / (1.f + expf(-g));
}

// ---------------- host ----------------
extern "C" void kernel_launch(void* const* d_in, const int* in_sizes, int n_in,
                              void* d_out, int out_size)
{
    const float* x     = (const float*)d_in[0];
    const float* Wq    = (const float*)d_in[1];
    const float* Wk    = (const float*)d_in[2];
    const float* Wv    = (const float*)d_in[3];
    const float* Wf1   = (const float*)d_in[4];
    const float* Wf2   = (const float*)d_in[5];
    const float* Wb    = (const float*)d_in[6];
    const float* Wg1   = (const float*)d_in[7];
    const float* Wg2   = (const float*)d_in[8];
    const float* bg    = (const float*)d_in[9];
    const float* onw   = (const float*)d_in[10];
    const float* Wout  = (const float*)d_in[11];
    const float* A_log = (const float*)d_in[12];
    const float* dtb   = (const float*)d_in[13];
    const float* qcw   = (const float*)d_in[14];
    const float* kcw   = (const float*)d_in[15];
    const float* vcw   = (const float*)d_in[16];
    float* out = (float*)d_out;

    float *Q, *K, *V, *Qc, *Kc, *Vc, *EG, *F1, *G1, *Gate, *Beta, *Y;
    cudaGetSymbolAddress((void**)&Q,   g_Q);
    cudaGetSymbolAddress((void**)&K,   g_K);
    cudaGetSymbolAddress((void**)&V,   g_V);
    cudaGetSymbolAddress((void**)&Qc,  g_Qc);
    cudaGetSymbolAddress((void**)&Kc,  g_Kc);
    cudaGetSymbolAddress((void**)&Vc,  g_Vc);
    cudaGetSymbolAddress((void**)&EG,  g_EG);
    cudaGetSymbolAddress((void**)&F1,  g_F1);
    cudaGetSymbolAddress((void**)&G1,  g_G1);
    cudaGetSymbolAddress((void**)&Gate,g_Gate);
    cudaGetSymbolAddress((void**)&Beta,g_Beta);
    cudaGetSymbolAddress((void**)&Y,   g_Y);

    dim3 gBig(HK / GBN, BT / GBM);     // (16, 32)
    dim3 gSm(VD / GBN, BT / GBM);      // (1, 32)

    // projections
    sgemm_nt<<<gBig, 256>>>(x, Wq, Q, BT, HK, DD);
    sgemm_nt<<<gBig, 256>>>(x, Wk, K, BT, HK, DD);
    sgemm_nt<<<gBig, 256>>>(x, Wv, V, BT, HV, DD);
    sgemm_nt<<<gSm, 256>>>(x, Wf1, F1, BT, VD, DD);
    sgemm_nt<<<gBig, 256>>>(F1, Wf2, EG, BT, HK, VD);
    sgemm_nt<<<gSm, 256>>>(x, Wg1, G1, BT, VD, DD);
    sgemm_nt<<<gBig, 256>>>(G1, Wg2, Gate, BT, HV, VD);
    beta_kernel<<<BT, 256>>>(x, Wb, Beta);

    // decay + conv/silu(/norm)
    decay_kernel<<<(BT * HK + 255) / 256, 256>>>(A_log, dtb, EG);
    convnorm_kernel<<<BT * HH, 128>>>(Q, qcw, Qc, 1);
    convnorm_kernel<<<BT * HH, 128>>>(K, kcw, Kc, 1);
    convnorm_kernel<<<BT * HH, 128>>>(V, vcw, Vc, 0);

    // sequential delta-rule scan
    scan_kernel<<<BB * HH * 4, 128>>>(Qc, Kc, Vc, EG, Beta, Y);

    // norm + gate, output projection
    rmsgate_kernel<<<BT * HH, 128>>>(Y, Gate, bg, onw);
    sgemm_nt<<<dim3(DD / GBN, BT / GBM), 256>>>(Y, Wout, out, BT, DD, HV);
}

// round 3
// speedup vs baseline: 2.0250x; 2.0250x over previous
#include <cuda_runtime.h>
#include <cuda_bf16.h>
#include <math.h>
#include <stdint.h>

// Problem constants
#define BB 2
#define TT 2048
#define DD 2048
#define HH 16
#define KD 128
#define VD 128
#define BT (BB*TT)          // 4096
#define HK (HH*KD)          // 2048
#define HV (HH*VD)          // 2048

// ---------------- scratch (device globals; no allocation allowed) ----------------
__device__ float g_Q[BT*HK];
__device__ float g_K[BT*HK];
__device__ float g_V[BT*HV];
__device__ float g_Qc[BT*HK];
__device__ float g_Kc[BT*HK];
__device__ float g_Vc[BT*HV];
__device__ float g_EG[BT*HK];
__device__ float g_F1[BT*VD];
__device__ float g_G1[BT*VD];
__device__ float g_Gate[BT*HV];
__device__ float g_Beta[BT*HH];
__device__ float g_Y[BT*HV];

// bf16 hi/lo split buffers
__device__ __nv_bfloat16 g_xh[BT*DD],  g_xl[BT*DD];
__device__ __nv_bfloat16 g_Yh[BT*HV],  g_Yl[BT*HV];
__device__ __nv_bfloat16 g_F1h[BT*VD], g_F1l[BT*VD];
__device__ __nv_bfloat16 g_G1h[BT*VD], g_G1l[BT*VD];
__device__ __nv_bfloat16 g_Wqh[HK*DD], g_Wql[HK*DD];
__device__ __nv_bfloat16 g_Wkh[HK*DD], g_Wkl[HK*DD];
__device__ __nv_bfloat16 g_Wvh[HV*DD], g_Wvl[HV*DD];
__device__ __nv_bfloat16 g_Woh[DD*HV], g_Wol[DD*HV];
__device__ __nv_bfloat16 g_Wf1h[VD*DD], g_Wf1l[VD*DD];
__device__ __nv_bfloat16 g_Wg1h[VD*DD], g_Wg1l[VD*DD];
__device__ __nv_bfloat16 g_Wf2h[HK*VD], g_Wf2l[HK*VD];
__device__ __nv_bfloat16 g_Wg2h[HV*VD], g_Wg2l[HV*VD];

// ================= helpers =================
#define SWZ(off) ((off) ^ (((off) >> 3) & 0x70))

__device__ __forceinline__ uint32_t sm2u(const void* p) {
    uint32_t a;
    asm("{ .reg .u64 t; cvta.to.shared.u64 t, %1; cvt.u32.u64 %0, t; }" : "=r"(a) : "l"(p));
    return a;
}

#define CP_ASYNC16(dst, src) \
    asm volatile("cp.async.cg.shared.global [%0], [%1], 16;" :: "r"(dst), "l"(src))
#define CP_COMMIT() asm volatile("cp.async.commit_group;")
#define CP_WAIT1()  asm volatile("cp.async.wait_group 1;")
#define CP_WAIT0()  asm volatile("cp.async.wait_group 0;")

#define LDMAT4(r0, r1, r2, r3, addr) \
    asm volatile("ldmatrix.sync.aligned.m8n8.x4.shared.b16 {%0,%1,%2,%3}, [%4];" \
        : "=r"(r0), "=r"(r1), "=r"(r2), "=r"(r3) : "r"(addr))

#define MMA_BF16(d, a, b) \
    asm volatile("mma.sync.aligned.m16n8k16.row.col.f32.bf16.bf16.f32 " \
        "{%0,%1,%2,%3},{%4,%5,%6,%7},{%8,%9},{%0,%1,%2,%3};" \
        : "+f"((d)[0]), "+f"((d)[1]), "+f"((d)[2]), "+f"((d)[3]) \
        : "r"((a)[0]), "r"((a)[1]), "r"((a)[2]), "r"((a)[3]), "r"((b)[0]), "r"((b)[1]))

// ================= split-bf16 HMMA GEMM =================
// C[M,N] = A[M,Kd]*B[N,Kd]^T, A~Ah+Al, B~Bh+Bl. BM=128, BN=NT*32, BK=64.
// 256 threads = 8 warps in 2(m) x 4(n); warp tile 64 x NT*8.
template<int NT>
__global__ __launch_bounds__(256, 1) void mmagemm(const __nv_bfloat16* __restrict__ Ah,
                                                  const __nv_bfloat16* __restrict__ Al,
                                                  const __nv_bfloat16* __restrict__ Bh,
                                                  const __nv_bfloat16* __restrict__ Bl,
                                                  float* __restrict__ C,
                                                  int N, int Kd)
{
    constexpr int BN  = NT * 32;
    constexpr int WN  = NT * 8;
    constexpr int ASZ = 128 * 128;      // bytes per A matrix per stage
    constexpr int BSZ = BN * 128;
    constexpr int STG = 2 * ASZ + 2 * BSZ;
    extern __shared__ __align__(1024) char smem[];
    const uint32_t sb = sm2u(smem);
    const int tid = threadIdx.x;
    const int m0 = blockIdx.y * 128, n0 = blockIdx.x * BN;

    auto prefetch = [&](int stg, int k0) {
        uint32_t b = sb + stg * STG;
        for (int idx = tid; idx < 1024; idx += 256) {
            int row = idx >> 3, ck = idx & 7;
            size_t go = ((size_t)(m0 + row) * Kd + k0) * 2 + ck * 16;
            uint32_t so = b + SWZ(row * 128 + ck * 16);
            CP_ASYNC16(so,       (const char*)Ah + go);
            CP_ASYNC16(so + ASZ, (const char*)Al + go);
        }
        for (int idx = tid; idx < BN * 8; idx += 256) {
            int row = idx >> 3, ck = idx & 7;
            size_t go = ((size_t)(n0 + row) * Kd + k0) * 2 + ck * 16;
            uint32_t so = b + 2 * ASZ + SWZ(row * 128 + ck * 16);
            CP_ASYNC16(so,       (const char*)Bh + go);
            CP_ASYNC16(so + BSZ, (const char*)Bl + go);
        }
    };

    const int wid = tid >> 5, lane = tid & 31;
    const int mw = wid >> 2, nw = wid & 3;
    const uint32_t xm = (lane & 7) * 16;
    const int arow = mw * 64 + (lane & 15);
    const int asel = ((lane >> 4) & 1) << 4;             // 0 or 16 bytes
    const int brow = nw * WN + (lane & 7) + (((lane >> 4) & 1) << 3);
    const int bsel = ((lane >> 3) & 1) << 4;

    float acc[4][NT][4];
#pragma unroll
    for (int mt = 0; mt < 4; mt++)
#pragma unroll
        for (int nt = 0; nt < NT; nt++)
#pragma unroll
            for (int q = 0; q < 4; q++) acc[mt][nt][q] = 0.f;

    const int iters = Kd >> 6;
    prefetch(0, 0);
    CP_COMMIT();

    for (int it = 0; it < iters; it++) {
        if (it + 1 < iters) {
            prefetch((it + 1) & 1, (it + 1) * 64);
            CP_COMMIT();
            CP_WAIT1();
        } else {
            CP_WAIT0();
        }
        __syncthreads();

        const uint32_t b = sb + (it & 1) * STG;
#pragma unroll
        for (int kk = 0; kk < 4; kk++) {
            const int koff = kk * 32;
            uint32_t ah[4][4], al[4][4];
#pragma unroll
            for (int mt = 0; mt < 4; mt++) {
                uint32_t ad = b + (uint32_t)(arow + mt * 16) * 128 + ((koff + asel) ^ xm);
                LDMAT4(ah[mt][0], ah[mt][1], ah[mt][2], ah[mt][3], ad);
                LDMAT4(al[mt][0], al[mt][1], al[mt][2], al[mt][3], ad + ASZ);
            }
            uint32_t bh[NT][2], bl[NT][2];
#pragma unroll
            for (int j = 0; j < NT / 2; j++) {
                uint32_t bd = b + 2 * ASZ + (uint32_t)(brow + j * 16) * 128 + ((koff + bsel) ^ xm);
                LDMAT4(bh[2*j][0], bh[2*j][1], bh[2*j+1][0], bh[2*j+1][1], bd);
                LDMAT4(bl[2*j][0], bl[2*j][1], bl[2*j+1][0], bl[2*j+1][1], bd + BSZ);
            }
#pragma unroll
            for (int mt = 0; mt < 4; mt++)
#pragma unroll
                for (int nt = 0; nt < NT; nt++) {
                    MMA_BF16(acc[mt][nt], ah[mt], bh[nt]);
                    MMA_BF16(acc[mt][nt], ah[mt], bl[nt]);
                    MMA_BF16(acc[mt][nt], al[mt], bh[nt]);
                }
        }
        __syncthreads();
    }

    // epilogue
#pragma unroll
    for (int mt = 0; mt < 4; mt++)
#pragma unroll
        for (int nt = 0; nt < NT; nt++) {
            int r = m0 + mw * 64 + mt * 16 + (lane >> 2);
            int c = n0 + nw * WN + nt * 8 + (lane & 3) * 2;
            *(float2*)&C[(size_t)r * N + c]       = make_float2(acc[mt][nt][0], acc[mt][nt][1]);
            *(float2*)&C[(size_t)(r + 8) * N + c] = make_float2(acc[mt][nt][2], acc[mt][nt][3]);
        }
}

// ---------------- split fp32 -> bf16 hi/lo ----------------
__global__ void split_kernel(const float* __restrict__ in,
                             __nv_bfloat16* __restrict__ h,
                             __nv_bfloat16* __restrict__ l, int n)
{
    int i = blockIdx.x * 256 + threadIdx.x;
    int stride = gridDim.x * 256;
    for (; i < n; i += stride) {
        float x = in[i];
        __nv_bfloat16 xh = __float2bfloat16(x);
        float r = x - __bfloat162float(xh);
        h[i] = xh;
        l[i] = __float2bfloat16(r);
    }
}

// ---------------- beta = sigmoid(x @ Wb^T), Wb: [H, D] ----------------
__global__ __launch_bounds__(256) void beta_kernel(const float* __restrict__ x,
                                                   const float* __restrict__ Wb,
                                                   float* __restrict__ Beta)
{
    const int m = blockIdx.x;
    const int tid = threadIdx.x;
    float acc[HH];
#pragma unroll
    for (int h = 0; h < HH; h++) acc[h] = 0.f;
    for (int d = tid; d < DD; d += 256) {
        float xv = x[(size_t)m * DD + d];
#pragma unroll
        for (int h = 0; h < HH; h++)
            acc[h] = fmaf(xv, Wb[(size_t)h * DD + d], acc[h]);
    }
    __shared__ float red[HH][9];
    const int warp = tid >> 5, lane = tid & 31;
#pragma unroll
    for (int h = 0; h < HH; h++) {
        float v = acc[h];
#pragma unroll
        for (int mask = 16; mask > 0; mask >>= 1)
            v += __shfl_xor_sync(0xffffffffu, v, mask);
        if (lane == 0) red[h][warp] = v;
    }
    __syncthreads();
    if (tid < HH) {
        float s = 0.f;
#pragma unroll
        for (int w = 0; w < 8; w++) s += red[tid][w];
        Beta[(size_t)m * HH + tid] = 1.f / (1.f + expf(-s));
    }
}

// ---------------- causal depthwise conv (k=4) + silu (+ optional l2norm) ----------------
__global__ __launch_bounds__(128) void convnorm_kernel(const float* __restrict__ in,
                                                       const float* __restrict__ w,
                                                       float* __restrict__ out,
                                                       int doNorm)
{
    const int m = blockIdx.x >> 4;
    const int h = blockIdx.x & 15;
    const int t = m & (TT - 1);
    const int c = threadIdx.x;
    const int col = h * 128 + c;
    const float* wp = &w[(size_t)(h * 128 + c) * 4];
    float acc = 0.f;
#pragma unroll
    for (int i = 0; i < 4; i++) {
        int tt = t - 3 + i;
        if (tt >= 0)
            acc = fmaf(in[(size_t)(m - 3 + i) * 2048 + col], wp[i], acc);
    }
    acc = acc / (1.f + expf(-acc));   // silu
    if (doNorm) {
        float ss = acc * acc;
#pragma unroll
        for (int mask = 16; mask > 0; mask >>= 1)
            ss += __shfl_xor_sync(0xffffffffu, ss, mask);
        __shared__ float sred[4];
        if ((threadIdx.x & 31) == 0) sred[threadIdx.x >> 5] = ss;
        __syncthreads();
        float tot = sred[0] + sred[1] + sred[2] + sred[3];
        float nrm = sqrtf(tot);
        acc = acc / fmaxf(nrm, 1e-12f);
    }
    out[(size_t)m * 2048 + col] = acc;
}

// ---------------- decay: EG = exp(-exp(A_log[h]) * softplus(g_raw + dt_bias)) ----------------
__global__ void decay_kernel(const float* __restrict__ A_log,
                             const float* __restrict__ dt_bias,
                             float* __restrict__ G)
{
    int idx = blockIdx.x * blockDim.x + threadIdx.x;
    if (idx >= BT * HK) return;
    int col = idx & (HK - 1);
    int h = col >> 7;
    float xv = G[idx] + dt_bias[col];
    float sp = (xv > 20.f) ? xv : log1pf(expf(xv));
    G[idx] = expf(-expf(A_log[h]) * sp);
}

// ---------------- KDA delta-rule scan ----------------
#define SCH 16
__global__ __launch_bounds__(128) void scan_kernel(const float* __restrict__ Qc,
                                                   const float* __restrict__ Kc,
                                                   const float* __restrict__ Vc,
                                                   const float* __restrict__ EG,
                                                   const float* __restrict__ Beta,
                                                   float* __restrict__ Y)
{
    const int chunkV = blockIdx.x & 3;
    const int bh = blockIdx.x >> 2;
    const int b = bh >> 4, h = bh & 15;
    const int tid = threadIdx.x;
    const int p = tid & 3;
    const int jj = tid >> 2;
    const int col = h * 128 + chunkV * 32 + jj;

    __shared__ float sk[SCH][144];
    __shared__ float sq[SCH][144];
    __shared__ float se[SCH][144];
    __shared__ float sv[SCH][32];
    __shared__ float sb[SCH];

    float S[32];
#pragma unroll
    for (int r = 0; r < 32; r++) S[r] = 0.f;

    const int pos = tid + ((tid >> 5) << 2);
    const int pbase = p * 36;

    for (int t0 = 0; t0 < TT; t0 += SCH) {
        __syncthreads();
#pragma unroll 4
        for (int s = 0; s < SCH; s++) {
            size_t off = (size_t)(b * TT + t0 + s) * 2048 + h * 128 + tid;
            sk[s][pos] = Kc[off];
            sq[s][pos] = Qc[off];
            se[s][pos] = EG[off];
        }
        if (tid < 32) {
#pragma unroll 4
            for (int s = 0; s < SCH; s++)
                sv[s][tid] = Vc[(size_t)(b * TT + t0 + s) * 2048 + h * 128 + chunkV * 32 + tid];
        }
        if (tid < SCH)
            sb[tid] = Beta[(size_t)(b * TT + t0 + tid) * HH + h];
        __syncthreads();

        for (int s = 0; s < SCH; s++) {
            const float* kp = &sk[s][pbase];
            const float* ep = &se[s][pbase];
            const float* qp = &sq[s][pbase];
            float d0 = 0.f, d1 = 0.f, d2 = 0.f, d3 = 0.f;
#pragma unroll
            for (int r = 0; r < 32; r += 4) {
                float s0 = S[r + 0] * ep[r + 0];
                float s1 = S[r + 1] * ep[r + 1];
                float s2 = S[r + 2] * ep[r + 2];
                float s3 = S[r + 3] * ep[r + 3];
                S[r + 0] = s0; S[r + 1] = s1; S[r + 2] = s2; S[r + 3] = s3;
                d0 = fmaf(kp[r + 0], s0, d0);
                d1 = fmaf(kp[r + 1], s1, d1);
                d2 = fmaf(kp[r + 2], s2, d2);
                d3 = fmaf(kp[r + 3], s3, d3);
            }
            float dot = (d0 + d1) + (d2 + d3);
            dot += __shfl_xor_sync(0xffffffffu, dot, 1);
            dot += __shfl_xor_sync(0xffffffffu, dot, 2);
            float u = sb[s] * (sv[s][jj] - dot);
            float o0 = 0.f, o1 = 0.f, o2 = 0.f, o3 = 0.f;
#pragma unroll
            for (int r = 0; r < 32; r += 4) {
                S[r + 0] = fmaf(kp[r + 0], u, S[r + 0]);
                S[r + 1] = fmaf(kp[r + 1], u, S[r + 1]);
                S[r + 2] = fmaf(kp[r + 2], u, S[r + 2]);
                S[r + 3] = fmaf(kp[r + 3], u, S[r + 3]);
                o0 = fmaf(qp[r + 0], S[r + 0], o0);
                o1 = fmaf(qp[r + 1], S[r + 1], o1);
                o2 = fmaf(qp[r + 2], S[r + 2], o2);
                o3 = fmaf(qp[r + 3], S[r + 3], o3);
            }
            float od = (o0 + o1) + (o2 + o3);
            od += __shfl_xor_sync(0xffffffffu, od, 1);
            od += __shfl_xor_sync(0xffffffffu, od, 2);
            if (p == 0)
                Y[(size_t)(b * TT + t0 + s) * 2048 + col] = od;
        }
    }
}

// ---------------- RMS norm over V, * o_norm_w, * sigmoid(gate + bg) ----------------
__global__ __launch_bounds__(128) void rmsgate_kernel(float* __restrict__ Y,
                                                      const float* __restrict__ Gate,
                                                      const float* __restrict__ bg,
                                                      const float* __restrict__ onw)
{
    const int m = blockIdx.x >> 4;
    const int h = blockIdx.x & 15;
    const int c = threadIdx.x;
    const int col = h * 128 + c;
    float y = Y[(size_t)m * 2048 + col];
    float ss = y * y;
#pragma unroll
    for (int mask = 16; mask > 0; mask >>= 1)
        ss += __shfl_xor_sync(0xffffffffu, ss, mask);
    __shared__ float sred[4];
    if ((threadIdx.x & 31) == 0) sred[threadIdx.x >> 5] = ss;
    __syncthreads();
    float tot = sred[0] + sred[1] + sred[2] + sred[3];
    float r = rsqrtf(tot * (1.f / 128.f) + 1.1920929e-07f);
    float g = Gate[(size_t)m * 2048 + col] + bg[col];
    Y[(size_t)m * 2048 + col] = y * r * onw[c] / (1.f + expf(-g));
}

// ---------------- host ----------------
extern "C" void kernel_launch(void* const* d_in, const int* in_sizes, int n_in,
                              void* d_out, int out_size)
{
    const float* x     = (const float*)d_in[0];
    const float* Wq    = (const float*)d_in[1];
    const float* Wk    = (const float*)d_in[2];
    const float* Wv    = (const float*)d_in[3];
    const float* Wf1   = (const float*)d_in[4];
    const float* Wf2   = (const float*)d_in[5];
    const float* Wb    = (const float*)d_in[6];
    const float* Wg1   = (const float*)d_in[7];
    const float* Wg2   = (const float*)d_in[8];
    const float* bg    = (const float*)d_in[9];
    const float* onw   = (const float*)d_in[10];
    const float* Wout  = (const float*)d_in[11];
    const float* A_log = (const float*)d_in[12];
    const float* dtb   = (const float*)d_in[13];
    const float* qcw   = (const float*)d_in[14];
    const float* kcw   = (const float*)d_in[15];
    const float* vcw   = (const float*)d_in[16];
    float* out = (float*)d_out;

    float *Q, *K, *V, *Qc, *Kc, *Vc, *EG, *F1, *G1, *Gate, *Beta, *Y;
    cudaGetSymbolAddress((void**)&Q,   g_Q);
    cudaGetSymbolAddress((void**)&K,   g_K);
    cudaGetSymbolAddress((void**)&V,   g_V);
    cudaGetSymbolAddress((void**)&Qc,  g_Qc);
    cudaGetSymbolAddress((void**)&Kc,  g_Kc);
    cudaGetSymbolAddress((void**)&Vc,  g_Vc);
    cudaGetSymbolAddress((void**)&EG,  g_EG);
    cudaGetSymbolAddress((void**)&F1,  g_F1);
    cudaGetSymbolAddress((void**)&G1,  g_G1);
    cudaGetSymbolAddress((void**)&Gate,g_Gate);
    cudaGetSymbolAddress((void**)&Beta,g_Beta);
    cudaGetSymbolAddress((void**)&Y,   g_Y);

    __nv_bfloat16 *xh,*xl,*Yh,*Yl,*F1h,*F1l,*G1h,*G1l;
    __nv_bfloat16 *Wqh,*Wql,*Wkh,*Wkl,*Wvh,*Wvl,*Woh,*Wol;
    __nv_bfloat16 *Wf1h,*Wf1l,*Wg1h,*Wg1l,*Wf2h,*Wf2l,*Wg2h,*Wg2l;
    cudaGetSymbolAddress((void**)&xh, g_xh);   cudaGetSymbolAddress((void**)&xl, g_xl);
    cudaGetSymbolAddress((void**)&Yh, g_Yh);   cudaGetSymbolAddress((void**)&Yl, g_Yl);
    cudaGetSymbolAddress((void**)&F1h, g_F1h); cudaGetSymbolAddress((void**)&F1l, g_F1l);
    cudaGetSymbolAddress((void**)&G1h, g_G1h); cudaGetSymbolAddress((void**)&G1l, g_G1l);
    cudaGetSymbolAddress((void**)&Wqh, g_Wqh); cudaGetSymbolAddress((void**)&Wql, g_Wql);
    cudaGetSymbolAddress((void**)&Wkh, g_Wkh); cudaGetSymbolAddress((void**)&Wkl, g_Wkl);
    cudaGetSymbolAddress((void**)&Wvh, g_Wvh); cudaGetSymbolAddress((void**)&Wvl, g_Wvl);
    cudaGetSymbolAddress((void**)&Woh, g_Woh); cudaGetSymbolAddress((void**)&Wol, g_Wol);
    cudaGetSymbolAddress((void**)&Wf1h, g_Wf1h); cudaGetSymbolAddress((void**)&Wf1l, g_Wf1l);
    cudaGetSymbolAddress((void**)&Wg1h, g_Wg1h); cudaGetSymbolAddress((void**)&Wg1l, g_Wg1l);
    cudaGetSymbolAddress((void**)&Wf2h, g_Wf2h); cudaGetSymbolAddress((void**)&Wf2l, g_Wf2l);
    cudaGetSymbolAddress((void**)&Wg2h, g_Wg2h); cudaGetSymbolAddress((void**)&Wg2l, g_Wg2l);

    // shared memory sizes
    const int SMEM4 = 2 * (2 * 128 * 128 + 2 * 128 * 128);   // 131072 (NT=4)
    const int SMEM2 = 2 * (2 * 128 * 128 + 2 * 64 * 128);    //  98304 (NT=2)
    cudaFuncSetAttribute(mmagemm<4>, cudaFuncAttributeMaxDynamicSharedMemorySize, SMEM4);
    cudaFuncSetAttribute(mmagemm<2>, cudaFuncAttributeMaxDynamicSharedMemorySize, SMEM2);

    // splits
    split_kernel<<<512, 256>>>(x,    xh,  xl,  BT * DD);
    split_kernel<<<512, 256>>>(Wq,   Wqh, Wql, HK * DD);
    split_kernel<<<512, 256>>>(Wk,   Wkh, Wkl, HK * DD);
    split_kernel<<<512, 256>>>(Wv,   Wvh, Wvl, HV * DD);
    split_kernel<<<512, 256>>>(Wout, Woh, Wol, DD * HV);
    split_kernel<<<128, 256>>>(Wf1,  Wf1h, Wf1l, VD * DD);
    split_kernel<<<128, 256>>>(Wg1,  Wg1h, Wg1l, VD * DD);
    split_kernel<<<128, 256>>>(Wf2,  Wf2h, Wf2l, HK * VD);
    split_kernel<<<128, 256>>>(Wg2,  Wg2h, Wg2l, HV * VD);

    dim3 gBig(HK / 128, BT / 128);   // (16, 32)
    dim3 gSm(VD / 64, BT / 128);     // (2, 32)

    // projections (HMMA tensor cores, split-bf16)
    mmagemm<4><<<gBig, 256, SMEM4>>>(xh, xl, Wqh, Wql, Q, HK, DD);
    mmagemm<4><<<gBig, 256, SMEM4>>>(xh, xl, Wkh, Wkl, K, HK, DD);
    mmagemm<4><<<gBig, 256, SMEM4>>>(xh, xl, Wvh, Wvl, V, HV, DD);
    mmagemm<2><<<gSm,  256, SMEM2>>>(xh, xl, Wf1h, Wf1l, F1, VD, DD);
    split_kernel<<<128, 256>>>(F1, F1h, F1l, BT * VD);
    mmagemm<4><<<gBig, 256, SMEM4>>>(F1h, F1l, Wf2h, Wf2l, EG, HK, VD);
    mmagemm<2><<<gSm,  256, SMEM2>>>(xh, xl, Wg1h, Wg1l, G1, VD, DD);
    split_kernel<<<128, 256>>>(G1, G1h, G1l, BT * VD);
    mmagemm<4><<<gBig, 256, SMEM4>>>(G1h, G1l, Wg2h, Wg2l, Gate, HV, VD);
    beta_kernel<<<BT, 256>>>(x, Wb, Beta);

    // decay + conv/silu(/norm)
    decay_kernel<<<(BT * HK + 255) / 256, 256>>>(A_log, dtb, EG);
    convnorm_kernel<<<BT * HH, 128>>>(Q, qcw, Qc, 1);
    convnorm_kernel<<<BT * HH, 128>>>(K, kcw, Kc, 1);
    convnorm_kernel<<<BT * HH, 128>>>(V, vcw, Vc, 0);

    // sequential delta-rule scan
    scan_kernel<<<BB * HH * 4, 128>>>(Qc, Kc, Vc, EG, Beta, Y);

    // norm + gate, split, output projection
    rmsgate_kernel<<<BT * HH, 128>>>(Y, Gate, bg, onw);
    split_kernel<<<512, 256>>>(Y, Yh, Yl, BT * HV);
    mmagemm<4><<<dim3(DD / 128, BT / 128), 256, SMEM4>>>(Yh, Yl, Woh, Wol, out, DD, HV);
}